// round 14
// baseline (speedup 1.0000x reference)
#include <cuda_runtime.h>
#include <cuda_fp16.h>
#include <math.h>
#include <cstdint>

#define BATCH 4
#define LSEQ  8192
#define DIM   1024
#define KSEL  6144
#define NUNSEL (LSEQ - KSEL)          // 2048
#define NTOK  (BATCH * LSEQ)
#define MBLK_PER_ROW (KSEL / 128)     // 48

// ---------------- scratch ----------------
__device__ float   g_scores[NTOK];
__device__ int     g_idx[BATCH * KSEL];      // sorted selected token ids
__device__ int     g_nidx[BATCH * NUNSEL];   // sorted unselected token ids
__device__ __half  g_xh[(size_t)NTOK * DIM];
__device__ __half  g_whT[DIM * DIM];

// ---------------- helpers ----------------
__device__ __forceinline__ uint32_t smem_u32(const void* p) {
    uint32_t a;
    asm("{ .reg .u64 t; cvta.to.shared.u64 t, %1; cvt.u32.u64 %0, t; }"
        : "=r"(a) : "l"(p));
    return a;
}
#define SW128(off) ((off) ^ (((off) >> 3) & 0x70))

#define CP_ASYNC16(smem, gmem)                                               \
    asm volatile("cp.async.cg.shared.global [%0], [%1], 16;"                 \
                 :: "r"(smem), "l"(gmem) : "memory")
#define CP_COMMIT()  asm volatile("cp.async.commit_group;" ::: "memory")
#define CP_WAIT(n)   asm volatile("cp.async.wait_group %0;" :: "n"(n) : "memory")

#define LDSM4(r0, r1, r2, r3, addr)                                          \
    asm volatile("ldmatrix.sync.aligned.m8n8.x4.shared.b16 {%0,%1,%2,%3}, [%4];" \
                 : "=r"(r0), "=r"(r1), "=r"(r2), "=r"(r3) : "r"(addr))

#define MMA_FP16(c, a, b)                                                    \
    asm volatile("mma.sync.aligned.m16n8k16.row.col.f32.f16.f16.f32 "        \
                 "{%0,%1,%2,%3}, {%4,%5,%6,%7}, {%8,%9}, {%0,%1,%2,%3};"     \
                 : "+f"((c)[0]), "+f"((c)[1]), "+f"((c)[2]), "+f"((c)[3])    \
                 : "r"((a)[0]), "r"((a)[1]), "r"((a)[2]), "r"((a)[3]),       \
                   "r"((b)[0]), "r"((b)[1]))

// gelu(tanh approx) == v * sigmoid(2u); exact algebraic identity.
__device__ __forceinline__ float gelu_fast(float v)
{
    float u = 0.7978845608028654f * (v + 0.044715f * v * v * v);
    return __fdividef(v, 1.0f + __expf(-2.0f * u));
}

// ---------------------------------------------------------------------------
// Kernel 1 (fused prep): blocks [0,4096) router scores + x->fp16;
// blocks [4096,5120) W[K,N] -> W^T fp16 [N,K] transpose.
// ---------------------------------------------------------------------------
#define SCORE_BLKS (NTOK / 8)            // 4096
__global__ __launch_bounds__(256) void prep_kernel(
    const float* __restrict__ x, const float* __restrict__ wr,
    const float* __restrict__ w)
{
    __shared__ float tile[32][33];
    if (blockIdx.x < SCORE_BLKS) {
        int warp = (blockIdx.x * blockDim.x + threadIdx.x) >> 5;
        int lane = threadIdx.x & 31;
        const float4* xr = (const float4*)(x + (size_t)warp * DIM);
        const float4* w4 = (const float4*)wr;
        uint2* hrow = (uint2*)(g_xh + (size_t)warp * DIM);
        float s = 0.f;
#pragma unroll
        for (int i = 0; i < 8; i++) {
            int d4 = lane + i * 32;
            float4 a = xr[d4];
            float4 b = w4[d4];
            s += a.x * b.x + a.y * b.y + a.z * b.z + a.w * b.w;
            __half2 p0 = __floats2half2_rn(a.x, a.y);
            __half2 p1 = __floats2half2_rn(a.z, a.w);
            uint2 hp;
            hp.x = *(uint32_t*)&p0;
            hp.y = *(uint32_t*)&p1;
            hrow[d4] = hp;
        }
#pragma unroll
        for (int o = 16; o; o >>= 1) s += __shfl_xor_sync(0xFFFFFFFFu, s, o);
        if (lane == 0) g_scores[warp] = s;
    } else {
        int bx = blockIdx.x - SCORE_BLKS;      // 0..1023
        int tx = threadIdx.x & 31, ty = threadIdx.x >> 5;
        int n0 = (bx & 31) * 32, k0 = (bx >> 5) * 32;
#pragma unroll
        for (int j = 0; j < 4; j++)
            tile[ty + j * 8][tx] = w[(size_t)(k0 + ty + j * 8) * DIM + n0 + tx];
        __syncthreads();
#pragma unroll
        for (int j = 0; j < 4; j++) {
            int n = n0 + ty + j * 8, k = k0 + tx;
            g_whT[(size_t)n * DIM + k] = __float2half_rn(tile[tx][ty + j * 8]);
        }
    }
}

// ---------------------------------------------------------------------------
// Kernel 2: top-k via 2-level radix select (exact stable-top-k) + sorted
// compaction by block-wide prefix scan. One 1024-thread block per batch row;
// thread t owns elements [8t, 8t+8).
// ---------------------------------------------------------------------------
#define CAND_MAX 1024

__device__ __forceinline__ void hist_select256(
    const int* h, int target, int lane, int* s_bin, int* s_r)
{
    int c8[8], seg = 0;
#pragma unroll
    for (int j = 0; j < 8; j++) { c8[j] = h[lane * 8 + j]; seg += c8[j]; }
    int v = seg;
#pragma unroll
    for (int o = 1; o < 32; o <<= 1) {
        int t = __shfl_down_sync(0xFFFFFFFFu, v, o);
        if (lane + o < 32) v += t;
    }
    int acc = v - seg;           // count in bins above this lane's segment
#pragma unroll
    for (int j = 7; j >= 0; j--) {
        int c = c8[j];
        if (acc < target && acc + c >= target) { *s_bin = lane * 8 + j; *s_r = target - acc; }
        acc += c;
    }
}

__global__ __launch_bounds__(1024) void flags_kernel()
{
    __shared__ uint32_t sk[LSEQ];          // 32 KB keys
    __shared__ int h[256];
    __shared__ int s_b1, s_r1, s_b2, s_r2;
    __shared__ uint32_t cK[CAND_MAX];
    __shared__ int cI[CAND_MAX];
    __shared__ int ccnt;
    __shared__ int wsum[32];

    const int row = blockIdx.x;
    const int tid = threadIdx.x;
    const int wid = tid >> 5, lane = tid & 31;
    const float* srow = g_scores + row * LSEQ;

    for (int i = tid; i < LSEQ; i += 1024) {
        uint32_t u = __float_as_uint(srow[i]);
        sk[i] = (u & 0x80000000u) ? ~u : (u | 0x80000000u);
    }
    if (tid < 256) h[tid] = 0;
    if (tid == 0) ccnt = 0;
    __syncthreads();

    for (int i = tid; i < LSEQ; i += 1024) atomicAdd(&h[sk[i] >> 24], 1);
    __syncthreads();
    if (tid < 32) hist_select256(h, KSEL, tid, &s_b1, &s_r1);
    __syncthreads();
    const uint32_t b1 = (uint32_t)s_b1;
    const int r1 = s_r1;
    if (tid < 256) h[tid] = 0;
    __syncthreads();
    for (int i = tid; i < LSEQ; i += 1024)
        if ((sk[i] >> 24) == b1) atomicAdd(&h[(sk[i] >> 16) & 0xFF], 1);
    __syncthreads();
    if (tid < 32) hist_select256(h, r1, tid, &s_b2, &s_r2);
    __syncthreads();
    const uint32_t T16 = (b1 << 8) | (uint32_t)s_b2;
    const int r2 = s_r2;

    for (int i = tid; i < LSEQ; i += 1024) {
        if ((sk[i] >> 16) == T16) {
            int p = atomicAdd(&ccnt, 1);
            if (p < CAND_MAX) { cK[p] = sk[i]; cI[p] = i; }
        }
    }
    __syncthreads();
    const int nc = ccnt;

    const int p0 = tid * 8;
    int sel[8], ls = 0;
#pragma unroll
    for (int j = 0; j < 8; j++) {
        int i = p0 + j;
        uint32_t k = sk[i];
        uint32_t t = k >> 16;
        int s;
        if (t > T16) s = 1;
        else if (t < T16) s = 0;
        else if (nc <= CAND_MAX) {
            int lr = 0;
            for (int q = 0; q < nc; q++)
                lr += (cK[q] > k) || (cK[q] == k && cI[q] < i);
            s = (lr < r2) ? 1 : 0;
        } else {
            int cnt = 0;
            for (int q = 0; q < LSEQ; q++)
                cnt += (sk[q] > k) || (sk[q] == k && q < i);
            s = (cnt < KSEL) ? 1 : 0;
        }
        sel[j] = s;
        ls += s;
    }

    int incl = ls;
#pragma unroll
    for (int o = 1; o < 32; o <<= 1) {
        int t = __shfl_up_sync(0xFFFFFFFFu, incl, o);
        if (lane >= o) incl += t;
    }
    if (lane == 31) wsum[wid] = incl;
    __syncthreads();
    if (wid == 0) {
        int v = wsum[lane];
#pragma unroll
        for (int o = 1; o < 32; o <<= 1) {
            int t = __shfl_up_sync(0xFFFFFFFFu, v, o);
            if (lane >= o) v += t;
        }
        wsum[lane] = v;   // inclusive scan of warp sums
    }
    __syncthreads();
    int sp = incl - ls + (wid ? wsum[wid - 1] : 0);
    int np = p0 - sp;
#pragma unroll
    for (int j = 0; j < 8; j++) {
        int gid = row * LSEQ + p0 + j;
        if (sel[j]) g_idx[row * KSEL + sp++] = gid;
        else        g_nidx[row * NUNSEL + np++] = gid;
    }
}

// ---------------------------------------------------------------------------
// Kernel 3: pass-through copy of unselected tokens (warp per list entry)
// ---------------------------------------------------------------------------
#define NCOPY (BATCH * NUNSEL)           // 8192
__global__ __launch_bounds__(256) void copy_kernel(
    const float* __restrict__ x, float* __restrict__ out)
{
    int w = (blockIdx.x * blockDim.x + threadIdx.x) >> 5;
    int lane = threadIdx.x & 31;
    if (w >= NCOPY) return;
    int tok = g_nidx[w];
    const float4* src = (const float4*)(x + (size_t)tok * DIM);
    float4*       dst = (float4*)(out + (size_t)tok * DIM);
#pragma unroll
    for (int i = 0; i < 8; i++) dst[lane + i * 32] = src[lane + i * 32];
}

// ---------------------------------------------------------------------------
// Kernel 4: persistent compacted fp16 mma.sync GEMM + gelu scatter epilogue.
// R12 core + CROSS-TILE software pipelining: the 3-stage cp.async ring runs
// continuously across tiles. Next tile's s_idx prefetched at chunk 1; chunks
// 14/15 issue next tile's chunk-0/1 fills; the epilogue overlaps them.
// ---------------------------------------------------------------------------
#define KC 64
#define NCHUNK (DIM / KC)               // 16
#define A_BYTES (128 * 128)
#define B_BYTES (128 * 128)
#define NSTAGE 3
#define STAGE_BYTES (A_BYTES + B_BYTES) // 32 KB
#define SMEM_DYN (1024 + NSTAGE * STAGE_BYTES)     // ~97 KB
#define NBLK_N (DIM / 128)                          // 8
#define NTILE (NBLK_N * BATCH * MBLK_PER_ROW)       // 1536

__global__ __launch_bounds__(256, 2) void gemm_mma_kernel(float* __restrict__ out)
{
    extern __shared__ char dsm[];
    __shared__ int s_idx[2][128];

    const int tid  = threadIdx.x;
    const int wid  = tid >> 5;
    const int lane = tid & 31;
    const int wm   = wid & 1;
    const int wn   = wid >> 1;
    uint32_t base = (smem_u32(dsm) + 1023u) & ~1023u;

    const uint32_t aLaneOff =
        (uint32_t)(((lane & 7) + ((lane >> 3) & 1) * 8) * 128 + (lane >> 4) * 16);
    const uint32_t bLaneOff =
        (uint32_t)(((lane & 7) + ((lane >> 4) & 1) * 8) * 128 + ((lane >> 3) & 1) * 16);

    // fill one chunk (A gather rows via idx list + B rows) into stage st
    auto fill = [&](const int* idx, int n0v, int kc, int st) {
        uint32_t aB = base + st * STAGE_BYTES;
        uint32_t bB = aB + A_BYTES;
#pragma unroll
        for (int it = 0; it < 4; it++) {          // A: 128 rows x 128B
            int i2 = tid + it * 256;
            int m = i2 >> 3, kq = (i2 & 7) * 8;
            int t = idx[m];
            CP_ASYNC16(aB + SW128((uint32_t)(m * 128 + kq * 2)),
                       g_xh + (size_t)t * DIM + kc + kq);
        }
#pragma unroll
        for (int it = 0; it < 4; it++) {          // B: 128 rows x 128B
            int i2 = tid + it * 256;
            int n = i2 >> 3, kq = (i2 & 7) * 8;
            CP_ASYNC16(bB + SW128((uint32_t)(n0v + n) * 0 +
                                  (uint32_t)(n * 128 + kq * 2)),
                       g_whT + (size_t)(n0v + n) * DIM + kc + kq);
        }
        CP_COMMIT();
    };

    int tile = blockIdx.x;
    if (tile >= NTILE) return;
    int par = 0;

    // prologue: first tile's indices + chunk 0/1 fills
    {
        int yb = tile >> 3;
        int b = yb / MBLK_PER_ROW, mblk = yb % MBLK_PER_ROW;
        if (tid < 128) s_idx[0][tid] = g_idx[b * KSEL + mblk * 128 + tid];
        __syncthreads();
        int n0 = (tile & 7) * 128;
        fill(s_idx[0], n0, 0, 0);
        fill(s_idx[0], n0, KC, 1);
    }

    int cons_st = 0;   // consumption stage (continuous ring)
    int fill_st = 2;   // fill stage for chunk c+2

#pragma unroll 1
    for (; tile < NTILE; tile += gridDim.x, par ^= 1) {
        const int n0 = (tile & 7) * 128;
        const int* idxp = s_idx[par];

        const int tn = tile + gridDim.x;
        const bool has_next = tn < NTILE;
        int n0n = 0, gn = 0;
        if (has_next) {
            int ybn = tn >> 3;
            n0n = (tn & 7) * 128;
            gn = (ybn / MBLK_PER_ROW) * KSEL + (ybn % MBLK_PER_ROW) * 128;
        }

        float acc[4][4][4];
#pragma unroll
        for (int i = 0; i < 4; i++)
#pragma unroll
            for (int j = 0; j < 4; j++)
#pragma unroll
                for (int q = 0; q < 4; q++) acc[i][j][q] = 0.f;

#pragma unroll 1
        for (int c = 0; c < NCHUNK; c++) {
            if (!has_next && c == NCHUNK - 1) { CP_WAIT(0); }
            else                              { CP_WAIT(1); }
            __syncthreads();     // single pipeline barrier per chunk

            const uint32_t aB = base + cons_st * STAGE_BYTES;
            const uint32_t bB = aB + A_BYTES;
#pragma unroll
            for (int ks = 0; ks < 4; ks++) {
                uint32_t afr[4][4];
#pragma unroll
                for (int mt = 0; mt < 4; mt++) {
                    uint32_t off = (uint32_t)((wm * 64 + mt * 16) * 128 + ks * 32) + aLaneOff;
                    LDSM4(afr[mt][0], afr[mt][1], afr[mt][2], afr[mt][3], aB + SW128(off));
                }
                uint32_t bfr[4][2];
#pragma unroll
                for (int np = 0; np < 2; np++) {
                    uint32_t off = (uint32_t)((wn * 32 + np * 16) * 128 + ks * 32) + bLaneOff;
                    LDSM4(bfr[2 * np][0], bfr[2 * np][1],
                          bfr[2 * np + 1][0], bfr[2 * np + 1][1], bB + SW128(off));
                }
#pragma unroll
                for (int mt = 0; mt < 4; mt++)
#pragma unroll
                    for (int nt = 0; nt < 4; nt++)
                        MMA_FP16(acc[mt][nt], afr[mt], bfr[nt]);
                if (ks == 0) {
                    // prefetch next tile's index list once prior epilogue is
                    // provably done with this buffer (chunk-0 barrier passed)
                    if (c == 1 && has_next && tid < 128)
                        s_idx[par ^ 1][tid] = g_idx[gn + tid];
                    int tc = c + 2;
                    if (tc < NCHUNK) {
                        fill(idxp, n0, tc * KC, fill_st);
                        fill_st = (fill_st + 1) % NSTAGE;
                    } else if (has_next) {
                        fill(s_idx[par ^ 1], n0n, (tc - NCHUNK) * KC, fill_st);
                        fill_st = (fill_st + 1) % NSTAGE;
                    }
                }
            }
            cons_st = (cons_st + 1) % NSTAGE;
        }

        // Epilogue (overlaps next tile's in-flight chunk 0/1 loads):
        const int colBase = n0 + wn * 32 + (lane & 3) * 2;
#pragma unroll
        for (int mt = 0; mt < 4; mt++) {
            int rl0 = wm * 64 + mt * 16 + (lane >> 2);
            int t0 = idxp[rl0];
            int t1 = idxp[rl0 + 8];
            float* o0 = out + (size_t)t0 * DIM;
            float* o1 = out + (size_t)t1 * DIM;
#pragma unroll
            for (int nt = 0; nt < 4; nt++) {
                int cc = colBase + nt * 8;
                float2 v0, v1;
                v0.x = gelu_fast(acc[mt][nt][0]);
                v0.y = gelu_fast(acc[mt][nt][1]);
                v1.x = gelu_fast(acc[mt][nt][2]);
                v1.y = gelu_fast(acc[mt][nt][3]);
                *(float2*)(o0 + cc) = v0;
                *(float2*)(o1 + cc) = v1;
            }
        }
    }
}

// ---------------------------------------------------------------------------
extern "C" void kernel_launch(void* const* d_in, const int* in_sizes, int n_in,
                              void* d_out, int out_size)
{
    const float* x  = (const float*)d_in[0];   // [4,8192,1024]
    const float* wr = (const float*)d_in[1];   // [1024]
    const float* wb = (const float*)d_in[2];   // [1024,1024]
    float* out = (float*)d_out;

    cudaFuncSetAttribute(gemm_mma_kernel,
                         cudaFuncAttributeMaxDynamicSharedMemorySize, SMEM_DYN);

    prep_kernel<<<SCORE_BLKS + 1024, 256>>>(x, wr, wb);
    flags_kernel<<<BATCH, 1024>>>();
    copy_kernel<<<NCOPY / 8, 256>>>(x, out);
    gemm_mma_kernel<<<296, 256, SMEM_DYN>>>(out);
}

// round 16
// speedup vs baseline: 1.0069x; 1.0069x over previous
#include <cuda_runtime.h>
#include <cuda_fp16.h>
#include <math.h>
#include <cstdint>

#define BATCH 4
#define LSEQ  8192
#define DIM   1024
#define KSEL  6144
#define NUNSEL (LSEQ - KSEL)          // 2048
#define NTOK  (BATCH * LSEQ)
#define MBLK_PER_ROW (KSEL / 128)     // 48

// ---------------- scratch ----------------
__device__ float   g_scores[NTOK];
__device__ int     g_idx[BATCH * KSEL];      // sorted selected token ids
__device__ int     g_nidx[BATCH * NUNSEL];   // sorted unselected token ids
__device__ __half  g_xh[(size_t)NTOK * DIM];
__device__ __half  g_whT[DIM * DIM];

// ---------------- helpers ----------------
__device__ __forceinline__ uint32_t smem_u32(const void* p) {
    uint32_t a;
    asm("{ .reg .u64 t; cvta.to.shared.u64 t, %1; cvt.u32.u64 %0, t; }"
        : "=r"(a) : "l"(p));
    return a;
}
#define SW128(off) ((off) ^ (((off) >> 3) & 0x70))

#define CP_ASYNC16(smem, gmem)                                               \
    asm volatile("cp.async.cg.shared.global [%0], [%1], 16;"                 \
                 :: "r"(smem), "l"(gmem) : "memory")
#define CP_COMMIT()  asm volatile("cp.async.commit_group;" ::: "memory")
#define CP_WAIT(n)   asm volatile("cp.async.wait_group %0;" :: "n"(n) : "memory")

#define LDSM4(r0, r1, r2, r3, addr)                                          \
    asm volatile("ldmatrix.sync.aligned.m8n8.x4.shared.b16 {%0,%1,%2,%3}, [%4];" \
                 : "=r"(r0), "=r"(r1), "=r"(r2), "=r"(r3) : "r"(addr))

#define MMA_FP16(c, a, b)                                                    \
    asm volatile("mma.sync.aligned.m16n8k16.row.col.f32.f16.f16.f32 "        \
                 "{%0,%1,%2,%3}, {%4,%5,%6,%7}, {%8,%9}, {%0,%1,%2,%3};"     \
                 : "+f"((c)[0]), "+f"((c)[1]), "+f"((c)[2]), "+f"((c)[3])    \
                 : "r"((a)[0]), "r"((a)[1]), "r"((a)[2]), "r"((a)[3]),       \
                   "r"((b)[0]), "r"((b)[1]))

// gelu(tanh approx) == v * sigmoid(2u); exact algebraic identity.
__device__ __forceinline__ float gelu_fast(float v)
{
    float u = 0.7978845608028654f * (v + 0.044715f * v * v * v);
    return __fdividef(v, 1.0f + __expf(-2.0f * u));
}

// ---------------------------------------------------------------------------
// Kernel 1 (fused prep): blocks [0,4096) router scores + x->fp16;
// blocks [4096,5120) W[K,N] -> W^T fp16 [N,K] transpose.
// ---------------------------------------------------------------------------
#define SCORE_BLKS (NTOK / 8)            // 4096
__global__ __launch_bounds__(256) void prep_kernel(
    const float* __restrict__ x, const float* __restrict__ wr,
    const float* __restrict__ w)
{
    __shared__ float tile[32][33];
    if (blockIdx.x < SCORE_BLKS) {
        int warp = (blockIdx.x * blockDim.x + threadIdx.x) >> 5;
        int lane = threadIdx.x & 31;
        const float4* xr = (const float4*)(x + (size_t)warp * DIM);
        const float4* w4 = (const float4*)wr;
        uint2* hrow = (uint2*)(g_xh + (size_t)warp * DIM);
        float s = 0.f;
#pragma unroll
        for (int i = 0; i < 8; i++) {
            int d4 = lane + i * 32;
            float4 a = xr[d4];
            float4 b = w4[d4];
            s += a.x * b.x + a.y * b.y + a.z * b.z + a.w * b.w;
            __half2 p0 = __floats2half2_rn(a.x, a.y);
            __half2 p1 = __floats2half2_rn(a.z, a.w);
            uint2 hp;
            hp.x = *(uint32_t*)&p0;
            hp.y = *(uint32_t*)&p1;
            hrow[d4] = hp;
        }
#pragma unroll
        for (int o = 16; o; o >>= 1) s += __shfl_xor_sync(0xFFFFFFFFu, s, o);
        if (lane == 0) g_scores[warp] = s;
    } else {
        int bx = blockIdx.x - SCORE_BLKS;      // 0..1023
        int tx = threadIdx.x & 31, ty = threadIdx.x >> 5;
        int n0 = (bx & 31) * 32, k0 = (bx >> 5) * 32;
#pragma unroll
        for (int j = 0; j < 4; j++)
            tile[ty + j * 8][tx] = w[(size_t)(k0 + ty + j * 8) * DIM + n0 + tx];
        __syncthreads();
#pragma unroll
        for (int j = 0; j < 4; j++) {
            int n = n0 + ty + j * 8, k = k0 + tx;
            g_whT[(size_t)n * DIM + k] = __float2half_rn(tile[tx][ty + j * 8]);
        }
    }
}

// ---------------------------------------------------------------------------
// Kernel 2: top-k via 2-level radix select (exact stable-top-k) + sorted
// compaction by block-wide prefix scan. One 1024-thread block per batch row;
// thread t owns elements [8t, 8t+8).
// ---------------------------------------------------------------------------
#define CAND_MAX 1024

__device__ __forceinline__ void hist_select256(
    const int* h, int target, int lane, int* s_bin, int* s_r)
{
    int c8[8], seg = 0;
#pragma unroll
    for (int j = 0; j < 8; j++) { c8[j] = h[lane * 8 + j]; seg += c8[j]; }
    int v = seg;
#pragma unroll
    for (int o = 1; o < 32; o <<= 1) {
        int t = __shfl_down_sync(0xFFFFFFFFu, v, o);
        if (lane + o < 32) v += t;
    }
    int acc = v - seg;           // count in bins above this lane's segment
#pragma unroll
    for (int j = 7; j >= 0; j--) {
        int c = c8[j];
        if (acc < target && acc + c >= target) { *s_bin = lane * 8 + j; *s_r = target - acc; }
        acc += c;
    }
}

__global__ __launch_bounds__(1024) void flags_kernel()
{
    __shared__ uint32_t sk[LSEQ];          // 32 KB keys
    __shared__ int h[256];
    __shared__ int s_b1, s_r1, s_b2, s_r2;
    __shared__ uint32_t cK[CAND_MAX];
    __shared__ int cI[CAND_MAX];
    __shared__ int ccnt;
    __shared__ int wsum[32];

    const int row = blockIdx.x;
    const int tid = threadIdx.x;
    const int wid = tid >> 5, lane = tid & 31;
    const float* srow = g_scores + row * LSEQ;

    for (int i = tid; i < LSEQ; i += 1024) {
        uint32_t u = __float_as_uint(srow[i]);
        sk[i] = (u & 0x80000000u) ? ~u : (u | 0x80000000u);
    }
    if (tid < 256) h[tid] = 0;
    if (tid == 0) ccnt = 0;
    __syncthreads();

    for (int i = tid; i < LSEQ; i += 1024) atomicAdd(&h[sk[i] >> 24], 1);
    __syncthreads();
    if (tid < 32) hist_select256(h, KSEL, tid, &s_b1, &s_r1);
    __syncthreads();
    const uint32_t b1 = (uint32_t)s_b1;
    const int r1 = s_r1;
    if (tid < 256) h[tid] = 0;
    __syncthreads();
    for (int i = tid; i < LSEQ; i += 1024)
        if ((sk[i] >> 24) == b1) atomicAdd(&h[(sk[i] >> 16) & 0xFF], 1);
    __syncthreads();
    if (tid < 32) hist_select256(h, r1, tid, &s_b2, &s_r2);
    __syncthreads();
    const uint32_t T16 = (b1 << 8) | (uint32_t)s_b2;
    const int r2 = s_r2;

    for (int i = tid; i < LSEQ; i += 1024) {
        if ((sk[i] >> 16) == T16) {
            int p = atomicAdd(&ccnt, 1);
            if (p < CAND_MAX) { cK[p] = sk[i]; cI[p] = i; }
        }
    }
    __syncthreads();
    const int nc = ccnt;

    const int p0 = tid * 8;
    int sel[8], ls = 0;
#pragma unroll
    for (int j = 0; j < 8; j++) {
        int i = p0 + j;
        uint32_t k = sk[i];
        uint32_t t = k >> 16;
        int s;
        if (t > T16) s = 1;
        else if (t < T16) s = 0;
        else if (nc <= CAND_MAX) {
            int lr = 0;
            for (int q = 0; q < nc; q++)
                lr += (cK[q] > k) || (cK[q] == k && cI[q] < i);
            s = (lr < r2) ? 1 : 0;
        } else {
            int cnt = 0;
            for (int q = 0; q < LSEQ; q++)
                cnt += (sk[q] > k) || (sk[q] == k && q < i);
            s = (cnt < KSEL) ? 1 : 0;
        }
        sel[j] = s;
        ls += s;
    }

    int incl = ls;
#pragma unroll
    for (int o = 1; o < 32; o <<= 1) {
        int t = __shfl_up_sync(0xFFFFFFFFu, incl, o);
        if (lane >= o) incl += t;
    }
    if (lane == 31) wsum[wid] = incl;
    __syncthreads();
    if (wid == 0) {
        int v = wsum[lane];
#pragma unroll
        for (int o = 1; o < 32; o <<= 1) {
            int t = __shfl_up_sync(0xFFFFFFFFu, v, o);
            if (lane >= o) v += t;
        }
        wsum[lane] = v;   // inclusive scan of warp sums
    }
    __syncthreads();
    int sp = incl - ls + (wid ? wsum[wid - 1] : 0);
    int np = p0 - sp;
#pragma unroll
    for (int j = 0; j < 8; j++) {
        int gid = row * LSEQ + p0 + j;
        if (sel[j]) g_idx[row * KSEL + sp++] = gid;
        else        g_nidx[row * NUNSEL + np++] = gid;
    }
}

// ---------------------------------------------------------------------------
// Kernel 3: pass-through copy of unselected tokens (warp per list entry)
// ---------------------------------------------------------------------------
#define NCOPY (BATCH * NUNSEL)           // 8192
__global__ __launch_bounds__(256) void copy_kernel(
    const float* __restrict__ x, float* __restrict__ out)
{
    int w = (blockIdx.x * blockDim.x + threadIdx.x) >> 5;
    int lane = threadIdx.x & 31;
    if (w >= NCOPY) return;
    int tok = g_nidx[w];
    const float4* src = (const float4*)(x + (size_t)tok * DIM);
    float4*       dst = (float4*)(out + (size_t)tok * DIM);
#pragma unroll
    for (int i = 0; i < 8; i++) dst[lane + i * 32] = src[lane + i * 32];
}

// ---------------------------------------------------------------------------
// Kernel 4: persistent compacted fp16 mma.sync GEMM + gelu scatter epilogue.
// R12-exact core (static striding, 3-stage ring, one barrier/chunk, fill at
// ks=0, 2 CTAs/SM) with ONE change: A-fragment double buffering — the 4 A
// LDSM4s for ks+1 issue before the ks MMAs, hiding most of the post-barrier
// shared-memory latency. (+16 regs only; B fragments stay single-buffered.)
// ---------------------------------------------------------------------------
#define KC 64
#define NCHUNK (DIM / KC)               // 16
#define A_BYTES (128 * 128)
#define B_BYTES (128 * 128)
#define NSTAGE 3
#define STAGE_BYTES (A_BYTES + B_BYTES) // 32 KB
#define SMEM_DYN (1024 + NSTAGE * STAGE_BYTES)     // ~97 KB
#define NBLK_N (DIM / 128)                          // 8
#define NTILE (NBLK_N * BATCH * MBLK_PER_ROW)       // 1536

__global__ __launch_bounds__(256, 2) void gemm_mma_kernel(float* __restrict__ out)
{
    extern __shared__ char dsm[];
    __shared__ int s_idx[2][128];

    const int tid  = threadIdx.x;
    const int wid  = tid >> 5;
    const int lane = tid & 31;
    const int wm   = wid & 1;
    const int wn   = wid >> 1;
    uint32_t base = (smem_u32(dsm) + 1023u) & ~1023u;

    const uint32_t aLaneOff =
        (uint32_t)(((lane & 7) + ((lane >> 3) & 1) * 8) * 128 + (lane >> 4) * 16);
    const uint32_t bLaneOff =
        (uint32_t)(((lane & 7) + ((lane >> 4) & 1) * 8) * 128 + ((lane >> 3) & 1) * 16);

    int par = 0;
#pragma unroll 1
    for (int tile = blockIdx.x; tile < NTILE; tile += gridDim.x, par ^= 1) {
        const int yb   = tile >> 3;
        const int n0   = (tile & 7) * 128;
        const int b    = yb / MBLK_PER_ROW;
        const int mblk = yb % MBLK_PER_ROW;

        if (tid < 128) s_idx[par][tid] = g_idx[b * KSEL + mblk * 128 + tid];
        __syncthreads();   // s_idx visible; prior tile fully done with smem

        const int* idxp = s_idx[par];

        float acc[4][4][4];
#pragma unroll
        for (int i = 0; i < 4; i++)
#pragma unroll
            for (int j = 0; j < 4; j++)
#pragma unroll
                for (int q = 0; q < 4; q++) acc[i][j][q] = 0.f;

        auto fill = [&](int c, int st) {
            int kc = c * KC;
            uint32_t aB = base + st * STAGE_BYTES;
            uint32_t bB = aB + A_BYTES;
#pragma unroll
            for (int it = 0; it < 4; it++) {          // A: 128 rows x 128B
                int idx = tid + it * 256;
                int m = idx >> 3, kq = (idx & 7) * 8;
                int t = idxp[m];
                CP_ASYNC16(aB + SW128((uint32_t)(m * 128 + kq * 2)),
                           g_xh + (size_t)t * DIM + kc + kq);
            }
#pragma unroll
            for (int it = 0; it < 4; it++) {          // B: 128 rows x 128B
                int idx = tid + it * 256;
                int n = idx >> 3, kq = (idx & 7) * 8;
                CP_ASYNC16(bB + SW128((uint32_t)(n * 128 + kq * 2)),
                           g_whT + (size_t)(n0 + n) * DIM + kc + kq);
            }
            CP_COMMIT();
        };

        fill(0, 0);
        fill(1, 1);

        uint32_t afr[2][4][4];          // double-buffered A fragments

        auto ldA = [&](uint32_t aB, int ks, int buf) {
#pragma unroll
            for (int mt = 0; mt < 4; mt++) {
                uint32_t off = (uint32_t)((wm * 64 + mt * 16) * 128 + ks * 32) + aLaneOff;
                LDSM4(afr[buf][mt][0], afr[buf][mt][1],
                      afr[buf][mt][2], afr[buf][mt][3], aB + SW128(off));
            }
        };

#pragma unroll 1
        for (int c = 0; c < NCHUNK; c++) {
            const int st = c % NSTAGE;
            if (c == NCHUNK - 1) { CP_WAIT(0); }
            else                 { CP_WAIT(1); }
            __syncthreads();     // single pipeline barrier per chunk

            const uint32_t aB = base + st * STAGE_BYTES;
            const uint32_t bB = aB + A_BYTES;

            ldA(aB, 0, 0);
#pragma unroll
            for (int ks = 0; ks < 4; ks++) {
                const int cur = ks & 1;
                uint32_t bfr[4][2];
#pragma unroll
                for (int np = 0; np < 2; np++) {
                    uint32_t off = (uint32_t)((wn * 32 + np * 16) * 128 + ks * 32) + bLaneOff;
                    LDSM4(bfr[2 * np][0], bfr[2 * np][1],
                          bfr[2 * np + 1][0], bfr[2 * np + 1][1], bB + SW128(off));
                }
                if (ks < 3) ldA(aB, ks + 1, cur ^ 1);   // prefetch next A frags
#pragma unroll
                for (int mt = 0; mt < 4; mt++)
#pragma unroll
                    for (int nt = 0; nt < 4; nt++)
                        MMA_FP16(acc[mt][nt], afr[cur][mt], bfr[nt]);
                if (ks == 0 && c + 2 < NCHUNK) fill(c + 2, (c + 2) % NSTAGE);
            }
        }

        // Epilogue: scatter gelu(acc); quad lanes cover full 32B sectors.
        const int colBase = n0 + wn * 32 + (lane & 3) * 2;
#pragma unroll
        for (int mt = 0; mt < 4; mt++) {
            int rl0 = wm * 64 + mt * 16 + (lane >> 2);
            int t0 = idxp[rl0];
            int t1 = idxp[rl0 + 8];
            float* o0 = out + (size_t)t0 * DIM;
            float* o1 = out + (size_t)t1 * DIM;
#pragma unroll
            for (int nt = 0; nt < 4; nt++) {
                int cc = colBase + nt * 8;
                float2 v0, v1;
                v0.x = gelu_fast(acc[mt][nt][0]);
                v0.y = gelu_fast(acc[mt][nt][1]);
                v1.x = gelu_fast(acc[mt][nt][2]);
                v1.y = gelu_fast(acc[mt][nt][3]);
                *(float2*)(o0 + cc) = v0;
                *(float2*)(o1 + cc) = v1;
            }
        }
    }
}

// ---------------------------------------------------------------------------
extern "C" void kernel_launch(void* const* d_in, const int* in_sizes, int n_in,
                              void* d_out, int out_size)
{
    const float* x  = (const float*)d_in[0];   // [4,8192,1024]
    const float* wr = (const float*)d_in[1];   // [1024]
    const float* wb = (const float*)d_in[2];   // [1024,1024]
    float* out = (float*)d_out;

    cudaFuncSetAttribute(gemm_mma_kernel,
                         cudaFuncAttributeMaxDynamicSharedMemorySize, SMEM_DYN);

    prep_kernel<<<SCORE_BLKS + 1024, 256>>>(x, wr, wb);
    flags_kernel<<<BATCH, 1024>>>();
    copy_kernel<<<NCOPY / 8, 256>>>(x, out);
    gemm_mma_kernel<<<296, 256, SMEM_DYN>>>(out);
}

// round 17
// speedup vs baseline: 1.0721x; 1.0648x over previous
#include <cuda_runtime.h>
#include <cuda_fp16.h>
#include <math.h>
#include <cstdint>

#define BATCH 4
#define LSEQ  8192
#define DIM   1024
#define KSEL  6144
#define NUNSEL (LSEQ - KSEL)          // 2048
#define NTOK  (BATCH * LSEQ)
#define MBLK_PER_ROW (KSEL / 128)     // 48

// ---------------- scratch ----------------
__device__ float   g_scores[NTOK];
__device__ int     g_idx[BATCH * KSEL];      // sorted selected token ids
__device__ int     g_nidx[BATCH * NUNSEL];   // sorted unselected token ids
__device__ int     g_tile;                   // dynamic tile counter
__device__ __half  g_xh[(size_t)NTOK * DIM];
__device__ __half  g_whT[DIM * DIM];

// ---------------- helpers ----------------
__device__ __forceinline__ uint32_t smem_u32(const void* p) {
    uint32_t a;
    asm("{ .reg .u64 t; cvta.to.shared.u64 t, %1; cvt.u32.u64 %0, t; }"
        : "=r"(a) : "l"(p));
    return a;
}
#define SW128(off) ((off) ^ (((off) >> 3) & 0x70))

#define CP_ASYNC16(smem, gmem)                                               \
    asm volatile("cp.async.cg.shared.global [%0], [%1], 16;"                 \
                 :: "r"(smem), "l"(gmem) : "memory")
#define CP_COMMIT()  asm volatile("cp.async.commit_group;" ::: "memory")
#define CP_WAIT(n)   asm volatile("cp.async.wait_group %0;" :: "n"(n) : "memory")

#define LDSM4(r0, r1, r2, r3, addr)                                          \
    asm volatile("ldmatrix.sync.aligned.m8n8.x4.shared.b16 {%0,%1,%2,%3}, [%4];" \
                 : "=r"(r0), "=r"(r1), "=r"(r2), "=r"(r3) : "r"(addr))

#define MMA_FP16(c, a, b)                                                    \
    asm volatile("mma.sync.aligned.m16n8k16.row.col.f32.f16.f16.f32 "        \
                 "{%0,%1,%2,%3}, {%4,%5,%6,%7}, {%8,%9}, {%0,%1,%2,%3};"     \
                 : "+f"((c)[0]), "+f"((c)[1]), "+f"((c)[2]), "+f"((c)[3])    \
                 : "r"((a)[0]), "r"((a)[1]), "r"((a)[2]), "r"((a)[3]),       \
                   "r"((b)[0]), "r"((b)[1]))

// gelu(tanh approx) == v * sigmoid(2u); exact algebraic identity.
__device__ __forceinline__ float gelu_fast(float v)
{
    float u = 0.7978845608028654f * (v + 0.044715f * v * v * v);
    return __fdividef(v, 1.0f + __expf(-2.0f * u));
}

// ---------------------------------------------------------------------------
// Kernel 1 (fused prep): blocks [0,4096) router scores + x->fp16;
// blocks [4096,5120) W[K,N] -> W^T fp16 [N,K] transpose. Block 0 resets the
// dynamic tile counter (fresh every graph replay).
// ---------------------------------------------------------------------------
#define SCORE_BLKS (NTOK / 8)            // 4096
__global__ __launch_bounds__(256) void prep_kernel(
    const float* __restrict__ x, const float* __restrict__ wr,
    const float* __restrict__ w)
{
    __shared__ float tile[32][33];
    if (blockIdx.x == 0 && threadIdx.x == 0) g_tile = 0;
    if (blockIdx.x < SCORE_BLKS) {
        int warp = (blockIdx.x * blockDim.x + threadIdx.x) >> 5;
        int lane = threadIdx.x & 31;
        const float4* xr = (const float4*)(x + (size_t)warp * DIM);
        const float4* w4 = (const float4*)wr;
        uint2* hrow = (uint2*)(g_xh + (size_t)warp * DIM);
        float s = 0.f;
#pragma unroll
        for (int i = 0; i < 8; i++) {
            int d4 = lane + i * 32;
            float4 a = xr[d4];
            float4 b = w4[d4];
            s += a.x * b.x + a.y * b.y + a.z * b.z + a.w * b.w;
            __half2 p0 = __floats2half2_rn(a.x, a.y);
            __half2 p1 = __floats2half2_rn(a.z, a.w);
            uint2 hp;
            hp.x = *(uint32_t*)&p0;
            hp.y = *(uint32_t*)&p1;
            hrow[d4] = hp;
        }
#pragma unroll
        for (int o = 16; o; o >>= 1) s += __shfl_xor_sync(0xFFFFFFFFu, s, o);
        if (lane == 0) g_scores[warp] = s;
    } else {
        int bx = blockIdx.x - SCORE_BLKS;      // 0..1023
        int tx = threadIdx.x & 31, ty = threadIdx.x >> 5;
        int n0 = (bx & 31) * 32, k0 = (bx >> 5) * 32;
#pragma unroll
        for (int j = 0; j < 4; j++)
            tile[ty + j * 8][tx] = w[(size_t)(k0 + ty + j * 8) * DIM + n0 + tx];
        __syncthreads();
#pragma unroll
        for (int j = 0; j < 4; j++) {
            int n = n0 + ty + j * 8, k = k0 + tx;
            g_whT[(size_t)n * DIM + k] = __float2half_rn(tile[tx][ty + j * 8]);
        }
    }
}

// ---------------------------------------------------------------------------
// Kernel 2: top-k via 2-level radix select (exact stable-top-k) + sorted
// compaction by block-wide prefix scan. One 1024-thread block per batch row;
// thread t owns elements [8t, 8t+8).
// ---------------------------------------------------------------------------
#define CAND_MAX 1024

__device__ __forceinline__ void hist_select256(
    const int* h, int target, int lane, int* s_bin, int* s_r)
{
    int c8[8], seg = 0;
#pragma unroll
    for (int j = 0; j < 8; j++) { c8[j] = h[lane * 8 + j]; seg += c8[j]; }
    int v = seg;
#pragma unroll
    for (int o = 1; o < 32; o <<= 1) {
        int t = __shfl_down_sync(0xFFFFFFFFu, v, o);
        if (lane + o < 32) v += t;
    }
    int acc = v - seg;           // count in bins above this lane's segment
#pragma unroll
    for (int j = 7; j >= 0; j--) {
        int c = c8[j];
        if (acc < target && acc + c >= target) { *s_bin = lane * 8 + j; *s_r = target - acc; }
        acc += c;
    }
}

__global__ __launch_bounds__(1024) void flags_kernel()
{
    __shared__ uint32_t sk[LSEQ];          // 32 KB keys
    __shared__ int h[256];
    __shared__ int s_b1, s_r1, s_b2, s_r2;
    __shared__ uint32_t cK[CAND_MAX];
    __shared__ int cI[CAND_MAX];
    __shared__ int ccnt;
    __shared__ int wsum[32];

    const int row = blockIdx.x;
    const int tid = threadIdx.x;
    const int wid = tid >> 5, lane = tid & 31;
    const float* srow = g_scores + row * LSEQ;

    for (int i = tid; i < LSEQ; i += 1024) {
        uint32_t u = __float_as_uint(srow[i]);
        sk[i] = (u & 0x80000000u) ? ~u : (u | 0x80000000u);
    }
    if (tid < 256) h[tid] = 0;
    if (tid == 0) ccnt = 0;
    __syncthreads();

    for (int i = tid; i < LSEQ; i += 1024) atomicAdd(&h[sk[i] >> 24], 1);
    __syncthreads();
    if (tid < 32) hist_select256(h, KSEL, tid, &s_b1, &s_r1);
    __syncthreads();
    const uint32_t b1 = (uint32_t)s_b1;
    const int r1 = s_r1;
    if (tid < 256) h[tid] = 0;
    __syncthreads();
    for (int i = tid; i < LSEQ; i += 1024)
        if ((sk[i] >> 24) == b1) atomicAdd(&h[(sk[i] >> 16) & 0xFF], 1);
    __syncthreads();
    if (tid < 32) hist_select256(h, r1, tid, &s_b2, &s_r2);
    __syncthreads();
    const uint32_t T16 = (b1 << 8) | (uint32_t)s_b2;
    const int r2 = s_r2;

    for (int i = tid; i < LSEQ; i += 1024) {
        if ((sk[i] >> 16) == T16) {
            int p = atomicAdd(&ccnt, 1);
            if (p < CAND_MAX) { cK[p] = sk[i]; cI[p] = i; }
        }
    }
    __syncthreads();
    const int nc = ccnt;

    const int p0 = tid * 8;
    int sel[8], ls = 0;
#pragma unroll
    for (int j = 0; j < 8; j++) {
        int i = p0 + j;
        uint32_t k = sk[i];
        uint32_t t = k >> 16;
        int s;
        if (t > T16) s = 1;
        else if (t < T16) s = 0;
        else if (nc <= CAND_MAX) {
            int lr = 0;
            for (int q = 0; q < nc; q++)
                lr += (cK[q] > k) || (cK[q] == k && cI[q] < i);
            s = (lr < r2) ? 1 : 0;
        } else {
            int cnt = 0;
            for (int q = 0; q < LSEQ; q++)
                cnt += (sk[q] > k) || (sk[q] == k && q < i);
            s = (cnt < KSEL) ? 1 : 0;
        }
        sel[j] = s;
        ls += s;
    }

    int incl = ls;
#pragma unroll
    for (int o = 1; o < 32; o <<= 1) {
        int t = __shfl_up_sync(0xFFFFFFFFu, incl, o);
        if (lane >= o) incl += t;
    }
    if (lane == 31) wsum[wid] = incl;
    __syncthreads();
    if (wid == 0) {
        int v = wsum[lane];
#pragma unroll
        for (int o = 1; o < 32; o <<= 1) {
            int t = __shfl_up_sync(0xFFFFFFFFu, v, o);
            if (lane >= o) v += t;
        }
        wsum[lane] = v;   // inclusive scan of warp sums
    }
    __syncthreads();
    int sp = incl - ls + (wid ? wsum[wid - 1] : 0);
    int np = p0 - sp;
#pragma unroll
    for (int j = 0; j < 8; j++) {
        int gid = row * LSEQ + p0 + j;
        if (sel[j]) g_idx[row * KSEL + sp++] = gid;
        else        g_nidx[row * NUNSEL + np++] = gid;
    }
}

// ---------------------------------------------------------------------------
// Kernel 3: fused GEMM + copy.
// Blocks [0, COPY_CTAS): pass-through copy of unselected tokens (overlapped
//   with the GEMM — these are wave-1 resident and exit early).
// Blocks [COPY_CTAS, COPY_CTAS+296): persistent compacted fp16 mma.sync GEMM
//   (R12-exact core) with DYNAMIC tile fetch so GEMM slots opening late
//   (displaced by copy CTAs) naturally take fewer tiles.
// ---------------------------------------------------------------------------
#define KC 64
#define NCHUNK (DIM / KC)               // 16
#define A_BYTES (128 * 128)
#define B_BYTES (128 * 128)
#define NSTAGE 3
#define STAGE_BYTES (A_BYTES + B_BYTES) // 32 KB
#define SMEM_DYN (1024 + NSTAGE * STAGE_BYTES)     // ~97 KB
#define NBLK_N (DIM / 128)                          // 8
#define NTILE (NBLK_N * BATCH * MBLK_PER_ROW)       // 1536
#define NCOPY (BATCH * NUNSEL)                      // 8192
#define COPY_CTAS 32
#define GEMM_CTAS 296

__global__ __launch_bounds__(256, 2) void gemm_mma_kernel(
    const float* __restrict__ x, float* __restrict__ out)
{
    extern __shared__ char dsm[];
    __shared__ int s_idx[2][128];
    __shared__ int s_tile;

    const int tid  = threadIdx.x;

    if (blockIdx.x < COPY_CTAS) {
        // ---- copy role: 32 CTAs x 8 warps; warp handles 32 strided tokens
        int warp = (blockIdx.x * 256 + tid) >> 5;   // 0..255
        int lane = tid & 31;
#pragma unroll 1
        for (int t = warp; t < NCOPY; t += COPY_CTAS * 8) {
            int tok = g_nidx[t];
            const float4* src = (const float4*)(x + (size_t)tok * DIM);
            float4*       dst = (float4*)(out + (size_t)tok * DIM);
#pragma unroll
            for (int i = 0; i < 8; i++) dst[lane + i * 32] = src[lane + i * 32];
        }
        return;
    }

    // ---- GEMM role (R12 core + dynamic tile fetch)
    const int wid  = tid >> 5;
    const int lane = tid & 31;
    const int wm   = wid & 1;
    const int wn   = wid >> 1;
    uint32_t base = (smem_u32(dsm) + 1023u) & ~1023u;

    const uint32_t aLaneOff =
        (uint32_t)(((lane & 7) + ((lane >> 3) & 1) * 8) * 128 + (lane >> 4) * 16);
    const uint32_t bLaneOff =
        (uint32_t)(((lane & 7) + ((lane >> 4) & 1) * 8) * 128 + ((lane >> 3) & 1) * 16);

    int par = 0;
#pragma unroll 1
    for (;; par ^= 1) {
        if (tid == 0) s_tile = atomicAdd(&g_tile, 1);
        __syncthreads();        // s_tile visible; prior tile done with smem
        const int tile = s_tile;
        if (tile >= NTILE) break;

        const int yb   = tile >> 3;
        const int n0   = (tile & 7) * 128;
        const int b    = yb / MBLK_PER_ROW;
        const int mblk = yb % MBLK_PER_ROW;

        if (tid < 128) s_idx[par][tid] = g_idx[b * KSEL + mblk * 128 + tid];
        __syncthreads();

        const int* idxp = s_idx[par];

        float acc[4][4][4];
#pragma unroll
        for (int i = 0; i < 4; i++)
#pragma unroll
            for (int j = 0; j < 4; j++)
#pragma unroll
                for (int q = 0; q < 4; q++) acc[i][j][q] = 0.f;

        auto fill = [&](int c, int st) {
            int kc = c * KC;
            uint32_t aB = base + st * STAGE_BYTES;
            uint32_t bB = aB + A_BYTES;
#pragma unroll
            for (int it = 0; it < 4; it++) {          // A: 128 rows x 128B
                int idx = tid + it * 256;
                int m = idx >> 3, kq = (idx & 7) * 8;
                int t = idxp[m];
                CP_ASYNC16(aB + SW128((uint32_t)(m * 128 + kq * 2)),
                           g_xh + (size_t)t * DIM + kc + kq);
            }
#pragma unroll
            for (int it = 0; it < 4; it++) {          // B: 128 rows x 128B
                int idx = tid + it * 256;
                int n = idx >> 3, kq = (idx & 7) * 8;
                CP_ASYNC16(bB + SW128((uint32_t)(n * 128 + kq * 2)),
                           g_whT + (size_t)(n0 + n) * DIM + kc + kq);
            }
            CP_COMMIT();
        };

        fill(0, 0);
        fill(1, 1);

#pragma unroll 1
        for (int c = 0; c < NCHUNK; c++) {
            const int st = c % NSTAGE;
            if (c == NCHUNK - 1) { CP_WAIT(0); }
            else                 { CP_WAIT(1); }
            __syncthreads();     // single pipeline barrier per chunk

            const uint32_t aB = base + st * STAGE_BYTES;
            const uint32_t bB = aB + A_BYTES;
#pragma unroll
            for (int ks = 0; ks < 4; ks++) {
                uint32_t afr[4][4];
#pragma unroll
                for (int mt = 0; mt < 4; mt++) {
                    uint32_t off = (uint32_t)((wm * 64 + mt * 16) * 128 + ks * 32) + aLaneOff;
                    LDSM4(afr[mt][0], afr[mt][1], afr[mt][2], afr[mt][3], aB + SW128(off));
                }
                uint32_t bfr[4][2];
#pragma unroll
                for (int np = 0; np < 2; np++) {
                    uint32_t off = (uint32_t)((wn * 32 + np * 16) * 128 + ks * 32) + bLaneOff;
                    LDSM4(bfr[2 * np][0], bfr[2 * np][1],
                          bfr[2 * np + 1][0], bfr[2 * np + 1][1], bB + SW128(off));
                }
#pragma unroll
                for (int mt = 0; mt < 4; mt++)
#pragma unroll
                    for (int nt = 0; nt < 4; nt++)
                        MMA_FP16(acc[mt][nt], afr[mt], bfr[nt]);
                if (ks == 0 && c + 2 < NCHUNK) fill(c + 2, (c + 2) % NSTAGE);
            }
        }

        // Epilogue: scatter gelu(acc); quad lanes cover full 32B sectors.
        const int colBase = n0 + wn * 32 + (lane & 3) * 2;
#pragma unroll
        for (int mt = 0; mt < 4; mt++) {
            int rl0 = wm * 64 + mt * 16 + (lane >> 2);
            int t0 = idxp[rl0];
            int t1 = idxp[rl0 + 8];
            float* o0 = out + (size_t)t0 * DIM;
            float* o1 = out + (size_t)t1 * DIM;
#pragma unroll
            for (int nt = 0; nt < 4; nt++) {
                int cc = colBase + nt * 8;
                float2 v0, v1;
                v0.x = gelu_fast(acc[mt][nt][0]);
                v0.y = gelu_fast(acc[mt][nt][1]);
                v1.x = gelu_fast(acc[mt][nt][2]);
                v1.y = gelu_fast(acc[mt][nt][3]);
                *(float2*)(o0 + cc) = v0;
                *(float2*)(o1 + cc) = v1;
            }
        }
    }
}

// ---------------------------------------------------------------------------
extern "C" void kernel_launch(void* const* d_in, const int* in_sizes, int n_in,
                              void* d_out, int out_size)
{
    const float* x  = (const float*)d_in[0];   // [4,8192,1024]
    const float* wr = (const float*)d_in[1];   // [1024]
    const float* wb = (const float*)d_in[2];   // [1024,1024]
    float* out = (float*)d_out;

    cudaFuncSetAttribute(gemm_mma_kernel,
                         cudaFuncAttributeMaxDynamicSharedMemorySize, SMEM_DYN);

    prep_kernel<<<SCORE_BLKS + 1024, 256>>>(x, wr, wb);
    flags_kernel<<<BATCH, 1024>>>();
    gemm_mma_kernel<<<COPY_CTAS + GEMM_CTAS, 256, SMEM_DYN>>>(x, out);
}